// round 3
// baseline (speedup 1.0000x reference)
#include <cuda_runtime.h>

#define BSZ    1024
#define TSTEPS 128
#define INDIM  256
#define HID    64
#define FREQ   10
#define OUTD   16
#define NW     266     // packed gate cols: i(64) | ste(64) | fre(10) | c(64) | o(64)
#define WPAD   320     // padded N so 5 x 64-col GEMM tiles need no load predicates

// Scratch (static device globals; no runtime allocation)
__device__ float d_pre[(size_t)BSZ * TSTEPS * NW];   // (t, b, 266) pre-activations
__device__ float d_Wpack[INDIM * WPAD];              // packed+padded input weights
__device__ float d_bpack[WPAD];                      // packed biases
__device__ float d_Upack[4 * HID * HID + FREQ * HID];// transposed recurrent weights
__device__ float d_cosT[TSTEPS * FREQ];
__device__ float d_sinT[TSTEPS * FREQ];

__device__ __forceinline__ float hsig(float x) {
    return fminf(fmaxf(x * (1.0f / 6.0f) + 0.5f, 0.0f), 1.0f);
}

// ---------------- pack input-side weights W_* -> d_Wpack [256 x 320] ----------------
__global__ void pack_w_kernel(const float* __restrict__ W_i,  const float* __restrict__ b_i,
                              const float* __restrict__ W_ste,const float* __restrict__ b_ste,
                              const float* __restrict__ W_fre,const float* __restrict__ b_fre,
                              const float* __restrict__ W_c,  const float* __restrict__ b_c,
                              const float* __restrict__ W_o,  const float* __restrict__ b_o)
{
    int n = blockIdx.x;      // 0..319
    int k = threadIdx.x;     // 0..255
    float w = 0.f, bias = 0.f;
    if (n < 64)       { w = W_i  [k * HID  + n];         bias = b_i  [n]; }
    else if (n < 128) { w = W_ste[k * HID  + (n - 64)];  bias = b_ste[n - 64]; }
    else if (n < 138) { w = W_fre[k * FREQ + (n - 128)]; bias = b_fre[n - 128]; }
    else if (n < 202) { w = W_c  [k * HID  + (n - 138)]; bias = b_c  [n - 138]; }
    else if (n < 266) { w = W_o  [k * HID  + (n - 202)]; bias = b_o  [n - 202]; }
    d_Wpack[k * WPAD + n] = w;
    if (k == 0) d_bpack[n] = bias;
}

// ---------------- transpose recurrent weights U_* -> [j][k] rows (float4-able) -------
__global__ void pack_u_kernel(const float* __restrict__ U_i, const float* __restrict__ U_ste,
                              const float* __restrict__ U_c, const float* __restrict__ U_o,
                              const float* __restrict__ U_fre)
{
    int idx = blockIdx.x * blockDim.x + threadIdx.x;   // 16 x 256 = 4096
    int j = idx >> 6, k = idx & 63;
    d_Upack[0 * 4096 + idx] = U_i  [k * HID + j];
    d_Upack[1 * 4096 + idx] = U_ste[k * HID + j];
    d_Upack[2 * 4096 + idx] = U_c  [k * HID + j];
    d_Upack[3 * 4096 + idx] = U_o  [k * HID + j];
    if (idx < FREQ * HID) {
        int f = idx >> 6, kk = idx & 63;
        d_Upack[4 * 4096 + idx] = U_fre[kk * FREQ + f];
    }
}

// ---------------- trig table, replicating reference fp32 arithmetic ------------------
__global__ void trig_kernel()
{
    int idx = blockIdx.x * blockDim.x + threadIdx.x;   // TSTEPS*FREQ = 1280
    if (idx < TSTEPS * FREQ) {
        int t = idx / FREQ, f = idx % FREQ;
        float fr = (float)f / 10.0f;                               // arange(F)/F in f32
        float omega = (6.28318530717958647692f * (float)(t + 1)) * fr; // (2pi*t)*freq order
        d_cosT[idx] = cosf(omega);
        d_sinT[idx] = sinf(omega);
    }
}

// ---------------- phase 1: pre[t*BS+b][0:266] = x(t,b) @ Wpack + bpack ---------------
// M = T*BS = 131072, K = 256, N = 320(padded). BM=128 BN=64 BK=16, 128 thr, 8x8 tiles.
__global__ __launch_bounds__(128) void gemm_kernel(const float* __restrict__ g1)
{
    const int BK = 16;
    __shared__ __align__(16) float As[BK * 132];   // transposed, padded stride
    __shared__ __align__(16) float Bs[BK * 64];

    const int bn = blockIdx.x * 64;     // n-tile fastest -> 5 blocks share A tile in L2
    const int bm = blockIdx.y * 128;
    const int tid = threadIdx.x;
    const int trow = tid >> 3;          // 0..15
    const int tcol = tid & 7;           // 0..7

    // row r = t*BSZ + b ; BM=128 divides BSZ so t is constant per block
    const int t     = bm >> 10;
    const int bbase = bm & 1023;

    float acc[8][8];
    #pragma unroll
    for (int i = 0; i < 8; i++)
        #pragma unroll
        for (int jn = 0; jn < 8; jn++) acc[i][jn] = 0.f;

    for (int kc = 0; kc < INDIM; kc += BK) {
        // A: 128 rows x 16 k, transposed into As[k][m]
        #pragma unroll
        for (int l = 0; l < 4; l++) {
            int idx = tid + l * 128;          // 0..511 float4 slots
            int row = idx >> 2;
            int c4  = (idx & 3) << 2;
            const float4 v = *(const float4*)(g1 +
                ((size_t)(bbase + row) * TSTEPS + t) * INDIM + kc + c4);
            As[(c4 + 0) * 132 + row] = v.x;
            As[(c4 + 1) * 132 + row] = v.y;
            As[(c4 + 2) * 132 + row] = v.z;
            As[(c4 + 3) * 132 + row] = v.w;
        }
        // B: 16 k x 64 n (padded Wpack -> no predicates)
        #pragma unroll
        for (int l = 0; l < 2; l++) {
            int idx = tid + l * 128;          // 0..255 float4 slots
            int k  = idx >> 4;
            int nc = (idx & 15) << 2;
            *(float4*)(&Bs[k * 64 + nc]) =
                *(const float4*)(d_Wpack + (size_t)(kc + k) * WPAD + bn + nc);
        }
        __syncthreads();

        #pragma unroll
        for (int k = 0; k < BK; k++) {
            float4 a0 = *(const float4*)(&As[k * 132 + trow * 8]);
            float4 a1 = *(const float4*)(&As[k * 132 + trow * 8 + 4]);
            float4 b0 = *(const float4*)(&Bs[k * 64 + tcol * 8]);
            float4 b1 = *(const float4*)(&Bs[k * 64 + tcol * 8 + 4]);
            float rm[8] = {a0.x,a0.y,a0.z,a0.w,a1.x,a1.y,a1.z,a1.w};
            float rn[8] = {b0.x,b0.y,b0.z,b0.w,b1.x,b1.y,b1.z,b1.w};
            #pragma unroll
            for (int i = 0; i < 8; i++)
                #pragma unroll
                for (int jn = 0; jn < 8; jn++)
                    acc[i][jn] = fmaf(rm[i], rn[jn], acc[i][jn]);
        }
        __syncthreads();
    }

    #pragma unroll
    for (int i = 0; i < 8; i++) {
        size_t r = (size_t)(bm + trow * 8 + i);
        #pragma unroll
        for (int jn = 0; jn < 8; jn++) {
            int n = bn + tcol * 8 + jn;
            if (n < NW) d_pre[r * NW + n] = acc[i][jn] + d_bpack[n];
        }
    }
}

// ---------------- phase 2: sequential scan, 1 block (64 thr) per batch element ------
__global__ __launch_bounds__(64) void recurrent_kernel(
    const float* __restrict__ U_a, const float* __restrict__ b_a,
    const float* __restrict__ W_p, const float* __restrict__ b_p,
    const float* __restrict__ fc_w, const float* __restrict__ fc_b,
    float* __restrict__ out)
{
    const int b = blockIdx.x;
    const int j = threadIdx.x;          // hidden unit owned by this thread

    __shared__ __align__(16) float sh_h[HID];
    __shared__ float sh_fre[FREQ];
    __shared__ float sh_ct[FREQ], sh_st[FREQ];
    __shared__ float sh_red[2];

    const float4* Ui4 = (const float4*)(d_Upack)         + j * 16;
    const float4* Us4 = (const float4*)(d_Upack + 4096)  + j * 16;
    const float4* Uc4 = (const float4*)(d_Upack + 8192)  + j * 16;
    const float4* Uo4 = (const float4*)(d_Upack + 12288) + j * 16;
    const float4* Uf4 = (const float4*)(d_Upack + 16384) + (j < FREQ ? j : 0) * 16;

    float S_re[FREQ], S_im[FREQ];
    #pragma unroll
    for (int f = 0; f < FREQ; f++) { S_re[f] = 0.f; S_im[f] = 0.f; }

    float ua[FREQ];
    #pragma unroll
    for (int f = 0; f < FREQ; f++) ua[f] = U_a[f];
    const float ba = b_a[j];

    sh_h[j] = 0.f;
    __syncthreads();

    float hn = 0.f;
    const float4* sh_h4 = (const float4*)sh_h;

    for (int tstep = 0; tstep < TSTEPS; tstep++) {
        const float* row = d_pre + ((size_t)tstep * BSZ + b) * NW;
        float acc_i = row[j];
        float acc_s = row[64 + j];
        float acc_c = row[138 + j];
        float acc_o = row[202 + j];
        float acc_f = (j < FREQ) ? row[128 + j] : 0.f;

        // h @ U_* : thread j computes output column j (U rows are contiguous)
        #pragma unroll
        for (int k4 = 0; k4 < 16; k4++) {
            float4 h4 = sh_h4[k4];
            float4 u;
            u = Ui4[k4];
            acc_i = fmaf(h4.x,u.x,acc_i); acc_i = fmaf(h4.y,u.y,acc_i);
            acc_i = fmaf(h4.z,u.z,acc_i); acc_i = fmaf(h4.w,u.w,acc_i);
            u = Us4[k4];
            acc_s = fmaf(h4.x,u.x,acc_s); acc_s = fmaf(h4.y,u.y,acc_s);
            acc_s = fmaf(h4.z,u.z,acc_s); acc_s = fmaf(h4.w,u.w,acc_s);
            u = Uc4[k4];
            acc_c = fmaf(h4.x,u.x,acc_c); acc_c = fmaf(h4.y,u.y,acc_c);
            acc_c = fmaf(h4.z,u.z,acc_c); acc_c = fmaf(h4.w,u.w,acc_c);
            u = Uo4[k4];
            acc_o = fmaf(h4.x,u.x,acc_o); acc_o = fmaf(h4.y,u.y,acc_o);
            acc_o = fmaf(h4.z,u.z,acc_o); acc_o = fmaf(h4.w,u.w,acc_o);
            if (j < FREQ) {
                u = Uf4[k4];
                acc_f = fmaf(h4.x,u.x,acc_f); acc_f = fmaf(h4.y,u.y,acc_f);
                acc_f = fmaf(h4.z,u.z,acc_f); acc_f = fmaf(h4.w,u.w,acc_f);
            }
        }

        float gi = hsig(acc_i);
        float gs = hsig(acc_s);
        float go = hsig(acc_o);
        float cc = gi * tanhf(acc_c);
        if (j < FREQ) {
            sh_fre[j] = hsig(acc_f);
            sh_ct[j]  = d_cosT[tstep * FREQ + j];
            sh_st[j]  = d_sinT[tstep * FREQ + j];
        }
        __syncthreads();   // A: sh_fre/ct/st visible; all sh_h reads done

        float acc_a = ba;
        #pragma unroll
        for (int f = 0; f < FREQ; f++) {
            float fr = gs * sh_fre[f];
            float re = fmaf(fr, S_re[f], cc * sh_ct[f]);
            float im = fmaf(fr, S_im[f], cc * sh_st[f]);
            S_re[f] = re; S_im[f] = im;
            acc_a = fmaf(fmaf(re, re, im * im), ua[f], acc_a);
        }
        hn = go * tanhf(acc_a);
        sh_h[j] = hn;      // safe: reads of sh_h all occurred before barrier A
        __syncthreads();   // B: h(t+1) visible for next iteration
    }

    // epilogue: out[b] = fc_b + b_p.fc_w + h . (W_p @ fc_w)
    float v = 0.f;
    #pragma unroll
    for (int o = 0; o < OUTD; o++) v = fmaf(W_p[j * OUTD + o], fc_w[o], v);
    float part = hn * v;
    #pragma unroll
    for (int off = 16; off > 0; off >>= 1)
        part += __shfl_down_sync(0xffffffffu, part, off);
    if ((j & 31) == 0) sh_red[j >> 5] = part;
    __syncthreads();
    if (j == 0) {
        float s0 = fc_b[0];
        #pragma unroll
        for (int o = 0; o < OUTD; o++) s0 = fmaf(b_p[o], fc_w[o], s0);
        out[b] = s0 + sh_red[0] + sh_red[1];
    }
}

extern "C" void kernel_launch(void* const* d_in, const int* in_sizes, int n_in,
                              void* d_out, int out_size)
{
    const float* g1    = (const float*)d_in[0];
    const float* W_i   = (const float*)d_in[1];
    const float* U_i   = (const float*)d_in[2];
    const float* b_i   = (const float*)d_in[3];
    const float* W_ste = (const float*)d_in[4];
    const float* U_ste = (const float*)d_in[5];
    const float* b_ste = (const float*)d_in[6];
    const float* W_fre = (const float*)d_in[7];
    const float* U_fre = (const float*)d_in[8];
    const float* b_fre = (const float*)d_in[9];
    const float* W_c   = (const float*)d_in[10];
    const float* U_c   = (const float*)d_in[11];
    const float* b_c   = (const float*)d_in[12];
    const float* W_o   = (const float*)d_in[13];
    const float* U_o   = (const float*)d_in[14];
    const float* b_o   = (const float*)d_in[15];
    const float* U_a   = (const float*)d_in[16];
    const float* b_a   = (const float*)d_in[17];
    const float* W_p   = (const float*)d_in[18];
    const float* b_p   = (const float*)d_in[19];
    const float* fc_w  = (const float*)d_in[20];
    const float* fc_b  = (const float*)d_in[21];

    pack_w_kernel<<<WPAD, 256>>>(W_i, b_i, W_ste, b_ste, W_fre, b_fre,
                                 W_c, b_c, W_o, b_o);
    pack_u_kernel<<<16, 256>>>(U_i, U_ste, U_c, U_o, U_fre);
    trig_kernel<<<5, 256>>>();
    gemm_kernel<<<dim3(5, 1024), 128>>>(g1);
    recurrent_kernel<<<BSZ, HID>>>(U_a, b_a, W_p, b_p, fc_w, fc_b, (float*)d_out);
}